// round 4
// baseline (speedup 1.0000x reference)
#include <cuda_runtime.h>
#include <math.h>

// Problem shapes (fixed by setup_inputs)
#define C_    16
#define H_    256
#define W_    512
#define ND_   32
#define HW_   (H_ * W_)          // 131072
#define NDHW_ (ND_ * HW_)        // 4194304
#define BASELINE_ 0.24f

// Channel-last copy of y: yT[h][w][c], 64B per pixel (16 fp32), 8 MiB total.
__device__ __align__(16) float g_yT[HW_ * C_];

// ---------------------------------------------------------------------------
// Kernel 0: transpose y [C,H,W] -> yT [H,W,C]
// One thread per pixel: 16 strided scalar loads (coalesced across warp per
// channel), one 64B contiguous vector store.
// ---------------------------------------------------------------------------
__global__ void transpose_y_kernel(const float* __restrict__ y) {
    int p = blockIdx.x * blockDim.x + threadIdx.x;   // over H*W
    if (p >= HW_) return;
    float4* dst = (float4*)(g_yT + (size_t)p * C_);
#pragma unroll
    for (int c4 = 0; c4 < 4; ++c4) {
        float4 v;
        v.x = __ldg(y + (c4 * 4 + 0) * HW_ + p);
        v.y = __ldg(y + (c4 * 4 + 1) * HW_ + p);
        v.z = __ldg(y + (c4 * 4 + 2) * HW_ + p);
        v.w = __ldg(y + (c4 * 4 + 3) * HW_ + p);
        dst[c4] = v;
    }
}

// ---------------------------------------------------------------------------
// Kernel 1: reference half — out[c, d, h, w] = x[c, h, w] for c in [0,16)
// float4 vectorized broadcast over the 32 disparities.
// ---------------------------------------------------------------------------
__global__ void ref_broadcast_kernel(const float4* __restrict__ x4,
                                     float4* __restrict__ out4) {
    int i = blockIdx.x * blockDim.x + threadIdx.x;   // index over C*H*W/4
    if (i >= (C_ * HW_) / 4) return;

    float4 v = x4[i];

    int w4 = i & (W_ / 4 - 1);          // 0..127
    int h  = (i >> 7) & (H_ - 1);       // 0..255
    int c  = i >> 15;                   // 0..15

    long base = (long)c * (NDHW_ / 4) + (long)h * (W_ / 4) + w4;
#pragma unroll 8
    for (int d = 0; d < ND_; ++d) {
        out4[base + (long)d * (HW_ / 4)] = v;
    }
}

// ---------------------------------------------------------------------------
// Kernel 2: warped half — one thread per (d,h,w), ALL 16 channels.
// Each corner gather is a 64B contiguous read from channel-last yT.
// ---------------------------------------------------------------------------
__global__ __launch_bounds__(256)
void warp_sample_kernel(const float* __restrict__ depth,
                        float* __restrict__ out) {
    int tid = blockIdx.x * blockDim.x + threadIdx.x;  // over ND*H*W
    if (tid >= NDHW_) return;

    int w = tid & (W_ - 1);
    int h = (tid >> 9) & (H_ - 1);
    int d = tid >> 17;

    const float PI = 3.14159265358979323846f;

    float theta = ((float)h + 0.5f) * (PI / (float)H_) - PI * 0.5f;
    float s, c;
    sincosf(theta, &s, &c);

    float dep = depth[tid];

    float dth = atanf((dep * s + BASELINE_) / (dep * c)) - theta;
    float d_v = dth * ((float)H_ / PI);

    float y_px = isfinite(d_v) ? ((float)h + d_v) : 0.0f;

    // normalize then unnormalize exactly like the reference (align_corners=False)
    float gx = (float)w / ((W_ - 1.0f) * 0.5f) - 1.0f;
    float gy = y_px     / ((H_ - 1.0f) * 0.5f) - 1.0f;
    float ix = ((gx + 1.0f) * (float)W_ - 1.0f) * 0.5f;
    float iy = ((gy + 1.0f) * (float)H_ - 1.0f) * 0.5f;

    float fx0 = floorf(ix);
    float fy0 = floorf(iy);
    float wx1 = ix - fx0;
    float wy1 = iy - fy0;
    float wx0 = 1.0f - wx1;
    float wy0 = 1.0f - wy1;

    int x0 = (int)fx0;
    int y0 = (int)fy0;
    int x1 = x0 + 1;
    int y1 = y0 + 1;

    bool vx0 = (x0 >= 0) & (x0 < W_);
    bool vx1 = (x1 >= 0) & (x1 < W_);
    bool vy0 = (y0 >= 0) & (y0 < H_);
    bool vy1 = (y1 >= 0) & (y1 < H_);

    float w00 = wx0 * wy0 * (float)(vx0 & vy0);
    float w10 = wx1 * wy0 * (float)(vx1 & vy0);
    float w01 = wx0 * wy1 * (float)(vx0 & vy1);
    float w11 = wx1 * wy1 * (float)(vx1 & vy1);

    int cx0 = min(max(x0, 0), W_ - 1);
    int cx1 = min(max(x1, 0), W_ - 1);
    int cy0 = min(max(y0, 0), H_ - 1);
    int cy1 = min(max(y1, 0), H_ - 1);

    const float4* p00 = (const float4*)(g_yT + (size_t)(cy0 * W_ + cx0) * C_);
    const float4* p10 = (const float4*)(g_yT + (size_t)(cy0 * W_ + cx1) * C_);
    const float4* p01 = (const float4*)(g_yT + (size_t)(cy1 * W_ + cx0) * C_);
    const float4* p11 = (const float4*)(g_yT + (size_t)(cy1 * W_ + cx1) * C_);

    float acc[C_];

#pragma unroll
    for (int c4 = 0; c4 < 4; ++c4) {
        float4 v = p00[c4];
        acc[c4 * 4 + 0] = w00 * v.x;
        acc[c4 * 4 + 1] = w00 * v.y;
        acc[c4 * 4 + 2] = w00 * v.z;
        acc[c4 * 4 + 3] = w00 * v.w;
    }
#pragma unroll
    for (int c4 = 0; c4 < 4; ++c4) {
        float4 v = p10[c4];
        acc[c4 * 4 + 0] += w10 * v.x;
        acc[c4 * 4 + 1] += w10 * v.y;
        acc[c4 * 4 + 2] += w10 * v.z;
        acc[c4 * 4 + 3] += w10 * v.w;
    }
#pragma unroll
    for (int c4 = 0; c4 < 4; ++c4) {
        float4 v = p01[c4];
        acc[c4 * 4 + 0] += w01 * v.x;
        acc[c4 * 4 + 1] += w01 * v.y;
        acc[c4 * 4 + 2] += w01 * v.z;
        acc[c4 * 4 + 3] += w01 * v.w;
    }
#pragma unroll
    for (int c4 = 0; c4 < 4; ++c4) {
        float4 v = p11[c4];
        acc[c4 * 4 + 0] += w11 * v.x;
        acc[c4 * 4 + 1] += w11 * v.y;
        acc[c4 * 4 + 2] += w11 * v.z;
        acc[c4 * 4 + 3] += w11 * v.w;
    }

    // out offset for channel (16+ch): (16+ch)*NDHW + d*HW + h*W + w
    long obase = 16L * NDHW_ + (long)d * HW_ + (long)h * W_ + w;
#pragma unroll
    for (int ch = 0; ch < C_; ++ch) {
        out[obase + (long)ch * NDHW_] = acc[ch];
    }
}

extern "C" void kernel_launch(void* const* d_in, const int* in_sizes, int n_in,
                              void* d_out, int out_size) {
    const float* x     = (const float*)d_in[0];
    const float* y     = (const float*)d_in[1];
    const float* depth = (const float*)d_in[2];
    float* out = (float*)d_out;

    {
        int total = HW_;
        int threads = 256;
        transpose_y_kernel<<<(total + threads - 1) / threads, threads>>>(y);
    }
    {
        int total = (C_ * HW_) / 4;
        int threads = 256;
        ref_broadcast_kernel<<<(total + threads - 1) / threads, threads>>>(
            (const float4*)x, (float4*)out);
    }
    {
        int total = NDHW_;
        int threads = 256;
        warp_sample_kernel<<<(total + threads - 1) / threads, threads>>>(depth, out);
    }
}

// round 5
// speedup vs baseline: 1.1857x; 1.1857x over previous
#include <cuda_runtime.h>
#include <math.h>

// Problem shapes (fixed by setup_inputs)
#define C_    16
#define H_    256
#define W_    512
#define ND_   32
#define HW_   (H_ * W_)          // 131072
#define NDHW_ (ND_ * HW_)        // 4194304
#define BASELINE_ 0.24f

// Tile geometry: one block = (one h, 64-wide w chunk, all 32 disparities, all 16 ch)
#define WCH   64                 // output w per block
#define ROWS_ 45                 // smem window rows: [h-1, h+43]; max needed y1 = h+42
#define COLS_ 66                 // smem window cols: [w0-1, w0+64]
#define CPAD_ 67                 // padded col stride in float4 units (bank spread)
#define PS_   (ROWS_ * CPAD_)    // plane stride (float4) = 3015

#define SMEM_BYTES (4 * PS_ * 16 + WCH * C_ * 4)   // 192960 + 4096 = 197056

// Channel-last copy of y: yT[h][w][c], 64B per pixel, 8 MiB.
__device__ __align__(16) float g_yT[HW_ * C_];

// ---------------------------------------------------------------------------
// Kernel 0: transpose y [C,H,W] -> yT [H,W,C]
// ---------------------------------------------------------------------------
__global__ void transpose_y_kernel(const float* __restrict__ y) {
    int p = blockIdx.x * blockDim.x + threadIdx.x;   // over H*W
    if (p >= HW_) return;
    float4* dst = (float4*)(g_yT + (size_t)p * C_);
#pragma unroll
    for (int c4 = 0; c4 < 4; ++c4) {
        float4 v;
        v.x = __ldg(y + (c4 * 4 + 0) * HW_ + p);
        v.y = __ldg(y + (c4 * 4 + 1) * HW_ + p);
        v.z = __ldg(y + (c4 * 4 + 2) * HW_ + p);
        v.w = __ldg(y + (c4 * 4 + 3) * HW_ + p);
        dst[c4] = v;
    }
}

// ---------------------------------------------------------------------------
// Kernel 1: fused cost volume.
// Stage the 45x66 pixel window (all 16 ch) in smem, then every (d, w) coord
// gathers its 4 bilinear corners from smem and writes both output halves.
// ---------------------------------------------------------------------------
__global__ __launch_bounds__(1024, 1)
void cost_volume_kernel(const float* __restrict__ x,
                        const float* __restrict__ depth,
                        float* __restrict__ out) {
    extern __shared__ float4 S[];                  // [4 planes][ROWS_][CPAD_]
    float* xs = (float*)(S + 4 * PS_);             // [16 ch][64 w] = 1024 floats

    int tid = threadIdx.x;
    int w0  = blockIdx.x * WCH;
    int h   = blockIdx.y;

    // ---- fill y window (dense, coalesced from channel-last yT) ----
    const float4* yT4 = (const float4*)g_yT;
    for (int idx = tid; idx < ROWS_ * COLS_ * 4; idx += 1024) {
        int ch4 = idx & 3;
        int col = (idx >> 2) % COLS_;
        int r   = idx / (COLS_ * 4);
        int gr = min(max(h - 1 + r, 0), H_ - 1);
        int gc = min(max(w0 - 1 + col, 0), W_ - 1);
        S[ch4 * PS_ + r * CPAD_ + col] = yT4[(size_t)(gr * W_ + gc) * 4 + ch4];
    }
    // ---- stage x chunk for the reference half ----
    {
        int ch = tid >> 6;         // 0..15
        int wl = tid & 63;         // 0..63
        xs[tid] = x[ch * HW_ + h * W_ + w0 + wl];
    }
    __syncthreads();

    const float PI = 3.14159265358979323846f;
    float theta = ((float)h + 0.5f) * (PI / (float)H_) - PI * 0.5f;
    float sth, cth;
    sincosf(theta, &sth, &cth);

#pragma unroll
    for (int i = 0; i < 2; ++i) {
        int cid = tid + i * 1024;          // 0..2047
        int d  = cid >> 6;                 // 0..31
        int wl = cid & 63;                 // 0..63
        int w  = w0 + wl;

        float dep = depth[(d * H_ + h) * W_ + w];

        float dth = atanf((dep * sth + BASELINE_) / (dep * cth)) - theta;
        float d_v = dth * ((float)H_ / PI);
        float y_px = isfinite(d_v) ? ((float)h + d_v) : 0.0f;

        // exact reference normalize/unnormalize sequence (align_corners=False)
        float gx = (float)w / ((W_ - 1.0f) * 0.5f) - 1.0f;
        float gy = y_px     / ((H_ - 1.0f) * 0.5f) - 1.0f;
        float ix = ((gx + 1.0f) * (float)W_ - 1.0f) * 0.5f;
        float iy = ((gy + 1.0f) * (float)H_ - 1.0f) * 0.5f;

        float fx0 = floorf(ix);
        float fy0 = floorf(iy);
        float wx1 = ix - fx0;
        float wy1 = iy - fy0;
        float wx0 = 1.0f - wx1;
        float wy0 = 1.0f - wy1;

        int x0 = (int)fx0;
        int y0 = (int)fy0;
        int x1 = x0 + 1;
        int y1 = y0 + 1;

        bool vx0 = (x0 >= 0) & (x0 < W_);
        bool vx1 = (x1 >= 0) & (x1 < W_);
        bool vy0 = (y0 >= 0) & (y0 < H_);
        bool vy1 = (y1 >= 0) & (y1 < H_);

        float w00 = wx0 * wy0 * (float)(vx0 & vy0);
        float w10 = wx1 * wy0 * (float)(vx1 & vy0);
        float w01 = wx0 * wy1 * (float)(vx0 & vy1);
        float w11 = wx1 * wy1 * (float)(vx1 & vy1);

        // window-relative indices (in-range whenever weight != 0; clamp = safety)
        int r0 = min(max(y0 - h + 1, 0), ROWS_ - 2);
        int c0 = min(max(x0 - w0 + 1, 0), COLS_ - 2);

        float acc[C_];
#pragma unroll
        for (int ch4 = 0; ch4 < 4; ++ch4) {
            const float4* P = S + ch4 * PS_;
            float4 v00 = P[r0 * CPAD_ + c0];
            float4 v10 = P[r0 * CPAD_ + c0 + 1];
            float4 v01 = P[(r0 + 1) * CPAD_ + c0];
            float4 v11 = P[(r0 + 1) * CPAD_ + c0 + 1];
            acc[ch4 * 4 + 0] = w00 * v00.x + w10 * v10.x + w01 * v01.x + w11 * v11.x;
            acc[ch4 * 4 + 1] = w00 * v00.y + w10 * v10.y + w01 * v01.y + w11 * v11.y;
            acc[ch4 * 4 + 2] = w00 * v00.z + w10 * v10.z + w01 * v01.z + w11 * v11.z;
            acc[ch4 * 4 + 3] = w00 * v00.w + w10 * v10.w + w01 * v01.w + w11 * v11.w;
        }

        long ob = (long)d * HW_ + (long)h * W_ + w;
#pragma unroll
        for (int ch = 0; ch < C_; ++ch) {
            out[(long)(16 + ch) * NDHW_ + ob] = acc[ch];       // warped half
            out[(long)ch        * NDHW_ + ob] = xs[ch * 64 + wl]; // reference half
        }
    }
}

extern "C" void kernel_launch(void* const* d_in, const int* in_sizes, int n_in,
                              void* d_out, int out_size) {
    const float* x     = (const float*)d_in[0];
    const float* y     = (const float*)d_in[1];
    const float* depth = (const float*)d_in[2];
    float* out = (float*)d_out;

    {
        int total = HW_;
        int threads = 256;
        transpose_y_kernel<<<(total + threads - 1) / threads, threads>>>(y);
    }
    {
        cudaFuncSetAttribute(cost_volume_kernel,
                             cudaFuncAttributeMaxDynamicSharedMemorySize,
                             SMEM_BYTES);
        dim3 grid(W_ / WCH, H_);   // (8, 256) = 2048 blocks
        cost_volume_kernel<<<grid, 1024, SMEM_BYTES>>>(x, depth, out);
    }
}

// round 6
// speedup vs baseline: 1.4639x; 1.2347x over previous
#include <cuda_runtime.h>
#include <math.h>

// Problem shapes (fixed by setup_inputs)
#define C_    16
#define H_    256
#define W_    512
#define ND_   32
#define HW_   (H_ * W_)          // 131072
#define NDHW_ (ND_ * HW_)        // 4194304
#define BASELINE_ 0.24f

// Tile: one block = (one h, 32-wide w chunk, all 32 d, all 16 ch)
#define WCH   32
#define ROWS_ 44                 // window rows y0 ∈ [h-1, h+42] (d_v ∈ (0,40.8])
#define RSF4  129                // row stride in float4 (4*32 + 1 pad) → bank grp (r+wl)%8
#define LSZ   (ROWS_ * RSF4)     // 5676 float4

#define SMEM_BYTES (LSZ * 16 + C_ * WCH * 4)   // 90816 + 2048 = 92864

// Channel-last copy of y: yT[h][w][c], 64B per pixel, 8 MiB.
__device__ __align__(16) float g_yT[HW_ * C_];

// ---------------------------------------------------------------------------
// Kernel 0: transpose y [C,H,W] -> yT [H,W,C]
// ---------------------------------------------------------------------------
__global__ void transpose_y_kernel(const float* __restrict__ y) {
    int p = blockIdx.x * blockDim.x + threadIdx.x;   // over H*W
    if (p >= HW_) return;
    float4* dst = (float4*)(g_yT + (size_t)p * C_);
#pragma unroll
    for (int c4 = 0; c4 < 4; ++c4) {
        float4 v;
        v.x = __ldg(y + (c4 * 4 + 0) * HW_ + p);
        v.y = __ldg(y + (c4 * 4 + 1) * HW_ + p);
        v.z = __ldg(y + (c4 * 4 + 2) * HW_ + p);
        v.w = __ldg(y + (c4 * 4 + 3) * HW_ + p);
        dst[c4] = v;
    }
}

// ---------------------------------------------------------------------------
// Kernel 1: fused cost volume with horizontally pre-lerped smem rows.
// L[r][ch4][wl] = wx0*vx0*yT[gr][x0][ch4..] + wx1*vx1*yT[gr][x1][ch4..]
// (zero for out-of-range rows). Gather = 2 rows x 4 float4 + vertical lerp.
// ---------------------------------------------------------------------------
__global__ __launch_bounds__(512, 2)
void cost_volume_kernel(const float* __restrict__ x,
                        const float* __restrict__ depth,
                        float* __restrict__ out) {
    extern __shared__ float4 L[];              // [ROWS_][4 ch4][32 wl] (+pad)
    float* xs = (float*)(L + LSZ);             // [16 ch][32 wl]

    int tid = threadIdx.x;
    int w0  = blockIdx.x * WCH;
    int h   = blockIdx.y;

    const float4* yT4 = (const float4*)g_yT;

    // ---- build pre-lerped window ----
    for (int idx = tid; idx < ROWS_ * WCH * 4; idx += 512) {
        int ch4 = idx & 3;
        int wl  = (idx >> 2) & (WCH - 1);
        int r   = idx >> 7;
        int gr  = h - 1 + r;

        float4 v = make_float4(0.f, 0.f, 0.f, 0.f);
        if (gr >= 0 && gr < H_) {
            int w = w0 + wl;
            // exact reference x math (align_corners=False)
            float gx  = (float)w / ((W_ - 1.0f) * 0.5f) - 1.0f;
            float ix  = ((gx + 1.0f) * (float)W_ - 1.0f) * 0.5f;
            float fx0 = floorf(ix);
            float wx1 = ix - fx0;
            float wx0 = 1.0f - wx1;
            int x0 = (int)fx0;
            int x1 = x0 + 1;
            float a0 = ((x0 >= 0) & (x0 < W_)) ? wx0 : 0.0f;
            float a1 = ((x1 >= 0) & (x1 < W_)) ? wx1 : 0.0f;
            int cx0 = min(max(x0, 0), W_ - 1);
            int cx1 = min(max(x1, 0), W_ - 1);
            const float4* row = yT4 + (size_t)gr * (W_ * 4);
            float4 p0 = row[cx0 * 4 + ch4];
            float4 p1 = row[cx1 * 4 + ch4];
            v.x = a0 * p0.x + a1 * p1.x;
            v.y = a0 * p0.y + a1 * p1.y;
            v.z = a0 * p0.z + a1 * p1.z;
            v.w = a0 * p0.w + a1 * p1.w;
        }
        L[r * RSF4 + ch4 * WCH + wl] = v;
    }
    // ---- stage x chunk for reference half ----
    {
        int ch = tid >> 5;          // 0..15
        int wl = tid & 31;
        xs[tid] = x[ch * HW_ + h * W_ + w0 + wl];
    }
    __syncthreads();

    const float PI = 3.14159265358979323846f;
    float theta = ((float)h + 0.5f) * (PI / (float)H_) - PI * 0.5f;
    float sth, cth;
    sincosf(theta, &sth, &cth);

#pragma unroll
    for (int i = 0; i < 2; ++i) {
        int cid = tid + i * 512;           // 0..1023
        int wl = cid & (WCH - 1);
        int d  = cid >> 5;                 // 0..31
        int w  = w0 + wl;

        float dep = depth[(d * H_ + h) * W_ + w];

        float dth = atanf((dep * sth + BASELINE_) / (dep * cth)) - theta;
        float d_v = dth * ((float)H_ / PI);
        float y_px = isfinite(d_v) ? ((float)h + d_v) : 0.0f;

        // exact reference y math (align_corners=False)
        float gy  = y_px / ((H_ - 1.0f) * 0.5f) - 1.0f;
        float iy  = ((gy + 1.0f) * (float)H_ - 1.0f) * 0.5f;
        float fy0 = floorf(iy);
        float wy1 = iy - fy0;
        float wy0 = 1.0f - wy1;
        int y0 = (int)fy0;

        int r0 = min(max(y0 - h + 1, 0), ROWS_ - 2);  // provably in range; clamp = safety
        const float4* L0 = L + r0 * RSF4;
        const float4* L1 = L0 + RSF4;

        float acc[C_];
#pragma unroll
        for (int ch4 = 0; ch4 < 4; ++ch4) {
            float4 u0 = L0[ch4 * WCH + wl];
            float4 u1 = L1[ch4 * WCH + wl];
            acc[ch4 * 4 + 0] = wy0 * u0.x + wy1 * u1.x;
            acc[ch4 * 4 + 1] = wy0 * u0.y + wy1 * u1.y;
            acc[ch4 * 4 + 2] = wy0 * u0.z + wy1 * u1.z;
            acc[ch4 * 4 + 3] = wy0 * u0.w + wy1 * u1.w;
        }

        long ob = (long)d * HW_ + (long)h * W_ + w;
#pragma unroll
        for (int ch = 0; ch < C_; ++ch) {
            out[(long)(16 + ch) * NDHW_ + ob] = acc[ch];          // warped half
            out[(long)ch        * NDHW_ + ob] = xs[ch * WCH + wl]; // reference half
        }
    }
}

extern "C" void kernel_launch(void* const* d_in, const int* in_sizes, int n_in,
                              void* d_out, int out_size) {
    const float* x     = (const float*)d_in[0];
    const float* y     = (const float*)d_in[1];
    const float* depth = (const float*)d_in[2];
    float* out = (float*)d_out;

    {
        int total = HW_;
        int threads = 256;
        transpose_y_kernel<<<(total + threads - 1) / threads, threads>>>(y);
    }
    {
        cudaFuncSetAttribute(cost_volume_kernel,
                             cudaFuncAttributeMaxDynamicSharedMemorySize,
                             SMEM_BYTES);
        dim3 grid(W_ / WCH, H_);   // (16, 256) = 4096 blocks
        cost_volume_kernel<<<grid, 512, SMEM_BYTES>>>(x, depth, out);
    }
}

// round 7
// speedup vs baseline: 1.8276x; 1.2484x over previous
#include <cuda_runtime.h>
#include <math.h>

// Problem shapes (fixed by setup_inputs)
#define C_    16
#define H_    256
#define W_    512
#define ND_   32
#define HW_   (H_ * W_)          // 131072
#define NDHW_ (ND_ * HW_)        // 4194304
#define BASELINE_ 0.24f

// Tile: one block = (8 output rows, 32-wide w chunk, all 32 d, all 16 ch)
#define WCH   32
#define HCH   8
#define ROWS_ 51                 // window rows [h0-1, h0+49]; y1 <= h0+7+42
#define RSF4  128                // row stride in float4 = 4 ch4 * 32 wl (== 0 mod 8)
#define LSZ   (ROWS_ * RSF4)     // 6528 float4
#define SMEM_BYTES (LSZ * 16)    // 104448 B -> 2 blocks/SM

// Channel-last copy of y: yT[h][w][c], 64B per pixel, 8 MiB.
__device__ __align__(16) float g_yT[HW_ * C_];

// ---------------------------------------------------------------------------
// Kernel 0: transpose y [C,H,W] -> yT [H,W,C]
// ---------------------------------------------------------------------------
__global__ void transpose_y_kernel(const float* __restrict__ y) {
    int p = blockIdx.x * blockDim.x + threadIdx.x;   // over H*W
    if (p >= HW_) return;
    float4* dst = (float4*)(g_yT + (size_t)p * C_);
#pragma unroll
    for (int c4 = 0; c4 < 4; ++c4) {
        float4 v;
        v.x = __ldg(y + (c4 * 4 + 0) * HW_ + p);
        v.y = __ldg(y + (c4 * 4 + 1) * HW_ + p);
        v.z = __ldg(y + (c4 * 4 + 2) * HW_ + p);
        v.w = __ldg(y + (c4 * 4 + 3) * HW_ + p);
        dst[c4] = v;
    }
}

// ---------------------------------------------------------------------------
// Kernel 1: fused cost volume. Pre-lerped rows for an 8-row output band in
// smem; gather = 2 conflict-free LDS.128 rows per ch4 + vertical lerp.
// ---------------------------------------------------------------------------
__global__ __launch_bounds__(512, 2)
void cost_volume_kernel(const float* __restrict__ x,
                        const float* __restrict__ depth,
                        float* __restrict__ out) {
    extern __shared__ float4 L[];              // [ROWS_][4 ch4][32 wl]

    int tid = threadIdx.x;
    int w0  = blockIdx.x * WCH;
    int h0  = blockIdx.y * HCH;

    const float4* yT4 = (const float4*)g_yT;

    // ---- fill pre-lerped window (STS group = lane%8 -> conflict-free) ----
    for (int k = tid; k < LSZ; k += 512) {
        int wl_low = k & 7;
        int ch4    = (k >> 3) & 3;
        int wl     = ((k >> 5) & 3) * 8 + wl_low;
        int r      = k >> 7;
        int gr     = h0 - 1 + r;

        float4 v = make_float4(0.f, 0.f, 0.f, 0.f);
        if (gr >= 0 && gr < H_) {
            int w = w0 + wl;
            // exact reference x math (align_corners=False)
            float gx  = (float)w / ((W_ - 1.0f) * 0.5f) - 1.0f;
            float ix  = ((gx + 1.0f) * (float)W_ - 1.0f) * 0.5f;
            float fx0 = floorf(ix);
            float wx1 = ix - fx0;
            float wx0 = 1.0f - wx1;
            int x0 = (int)fx0;
            int x1 = x0 + 1;
            float a0 = ((x0 >= 0) & (x0 < W_)) ? wx0 : 0.0f;
            float a1 = ((x1 >= 0) & (x1 < W_)) ? wx1 : 0.0f;
            int cx0 = min(max(x0, 0), W_ - 1);
            int cx1 = min(max(x1, 0), W_ - 1);
            const float4* row = yT4 + (size_t)gr * (W_ * 4);
            float4 p0 = row[cx0 * 4 + ch4];
            float4 p1 = row[cx1 * 4 + ch4];
            v.x = a0 * p0.x + a1 * p1.x;
            v.y = a0 * p0.y + a1 * p1.y;
            v.z = a0 * p0.z + a1 * p1.z;
            v.w = a0 * p0.w + a1 * p1.w;
        }
        L[r * RSF4 + ch4 * WCH + wl] = v;
    }
    __syncthreads();

    const float PI = 3.14159265358979323846f;

#pragma unroll
    for (int i = 0; i < (HCH * ND_ * WCH) / 512; ++i) {    // 16 iters
        int cid = tid + i * 512;
        int wl = cid & (WCH - 1);
        int d  = (cid >> 5) & (ND_ - 1);
        int hh = cid >> 10;
        int h  = h0 + hh;
        int w  = w0 + wl;

        float theta = ((float)h + 0.5f) * (PI / (float)H_) - PI * 0.5f;
        float sth, cth;
        sincosf(theta, &sth, &cth);

        float dep = depth[(d * H_ + h) * W_ + w];

        float dth = atanf((dep * sth + BASELINE_) / (dep * cth)) - theta;
        float d_v = dth * ((float)H_ / PI);
        float y_px = isfinite(d_v) ? ((float)h + d_v) : 0.0f;

        // exact reference y math (align_corners=False)
        float gy  = y_px / ((H_ - 1.0f) * 0.5f) - 1.0f;
        float iy  = ((gy + 1.0f) * (float)H_ - 1.0f) * 0.5f;
        float fy0 = floorf(iy);
        float wy1 = iy - fy0;
        float wy0 = 1.0f - wy1;
        int y0 = (int)fy0;

        int r0 = min(max(y0 - h0 + 1, 0), ROWS_ - 2);  // provably in range
        const float4* L0 = L + r0 * RSF4;
        const float4* L1 = L0 + RSF4;

        float acc[C_];
#pragma unroll
        for (int ch4 = 0; ch4 < 4; ++ch4) {
            float4 u0 = L0[ch4 * WCH + wl];
            float4 u1 = L1[ch4 * WCH + wl];
            acc[ch4 * 4 + 0] = wy0 * u0.x + wy1 * u1.x;
            acc[ch4 * 4 + 1] = wy0 * u0.y + wy1 * u1.y;
            acc[ch4 * 4 + 2] = wy0 * u0.z + wy1 * u1.z;
            acc[ch4 * 4 + 3] = wy0 * u0.w + wy1 * u1.w;
        }

        long ob = (long)d * HW_ + (long)h * W_ + w;
        const float* xp = x + h * W_ + w;
#pragma unroll
        for (int ch = 0; ch < C_; ++ch) {
            out[(long)(16 + ch) * NDHW_ + ob] = acc[ch];            // warped half
            out[(long)ch        * NDHW_ + ob] = __ldg(xp + ch * HW_); // ref half (L1-hit)
        }
    }
}

extern "C" void kernel_launch(void* const* d_in, const int* in_sizes, int n_in,
                              void* d_out, int out_size) {
    const float* x     = (const float*)d_in[0];
    const float* y     = (const float*)d_in[1];
    const float* depth = (const float*)d_in[2];
    float* out = (float*)d_out;

    {
        int total = HW_;
        int threads = 256;
        transpose_y_kernel<<<(total + threads - 1) / threads, threads>>>(y);
    }
    {
        cudaFuncSetAttribute(cost_volume_kernel,
                             cudaFuncAttributeMaxDynamicSharedMemorySize,
                             SMEM_BYTES);
        dim3 grid(W_ / WCH, H_ / HCH);   // (16, 32) = 512 blocks
        cost_volume_kernel<<<grid, 512, SMEM_BYTES>>>(x, depth, out);
    }
}

// round 8
// speedup vs baseline: 1.9649x; 1.0751x over previous
#include <cuda_runtime.h>
#include <math.h>

// Problem shapes (fixed by setup_inputs)
#define C_    16
#define H_    256
#define W_    512
#define ND_   32
#define HW_   (H_ * W_)          // 131072
#define NDHW_ (ND_ * HW_)        // 4194304
#define BASELINE_ 0.24f

// Tile: one block = (8 output rows, 32-wide w chunk, all 32 d, all 16 ch)
#define WCH   32
#define HCH   8
#define ROWS_ 51                 // window rows [h0-1, h0+49]; max y1 = h0+7+42
#define RSF4  128                // row stride in float4 (== 0 mod 8 -> gather grp = wl%8)
#define LSZ   (ROWS_ * RSF4)     // 6528 float4
#define SMEM_BYTES (LSZ * 16 + HCH * 8)   // window + 8x float2 sincos

// Channel-last copy of y: yT[h][w][c], 64B per pixel, 8 MiB.
__device__ __align__(16) float g_yT[HW_ * C_];

// ---------------------------------------------------------------------------
// Kernel 0: transpose y [C,H,W] -> yT [H,W,C]
// ---------------------------------------------------------------------------
__global__ void transpose_y_kernel(const float* __restrict__ y) {
    int p = blockIdx.x * blockDim.x + threadIdx.x;   // over H*W
    if (p >= HW_) return;
    float4* dst = (float4*)(g_yT + (size_t)p * C_);
#pragma unroll
    for (int c4 = 0; c4 < 4; ++c4) {
        float4 v;
        v.x = __ldg(y + (c4 * 4 + 0) * HW_ + p);
        v.y = __ldg(y + (c4 * 4 + 1) * HW_ + p);
        v.z = __ldg(y + (c4 * 4 + 2) * HW_ + p);
        v.w = __ldg(y + (c4 * 4 + 3) * HW_ + p);
        dst[c4] = v;
    }
}

// ---------------------------------------------------------------------------
// Kernel 1: fused cost volume, software-pipelined depth, hoisted sincos.
// ---------------------------------------------------------------------------
__global__ __launch_bounds__(512, 2)
void cost_volume_kernel(const float* __restrict__ x,
                        const float* __restrict__ depth,
                        float* __restrict__ out) {
    extern __shared__ float4 L[];              // [ROWS_][4 ch4][32 wl]
    float2* thsc = (float2*)(L + LSZ);         // [HCH] {sin, cos}

    int tid = threadIdx.x;
    int w0  = blockIdx.x * WCH;
    int h0  = blockIdx.y * HCH;

    const float PI = 3.14159265358979323846f;
    const float4* yT4 = (const float4*)g_yT;

    // ---- per-band sincos table ----
    if (tid < HCH) {
        float theta = ((float)(h0 + tid) + 0.5f) * (PI / (float)H_) - PI * 0.5f;
        float s, c;
        sincosf(theta, &s, &c);
        thsc[tid] = make_float2(s, c);
    }

    // ---- fill pre-lerped window (STS group = lane%8 -> conflict-free) ----
    for (int k = tid; k < LSZ; k += 512) {
        int wl_low = k & 7;
        int ch4    = (k >> 3) & 3;
        int wl     = ((k >> 5) & 3) * 8 + wl_low;
        int r      = k >> 7;
        int gr     = h0 - 1 + r;

        float4 v = make_float4(0.f, 0.f, 0.f, 0.f);
        if (gr >= 0 && gr < H_) {
            int w = w0 + wl;
            // exact reference x math (align_corners=False)
            float gx  = (float)w / ((W_ - 1.0f) * 0.5f) - 1.0f;
            float ix  = ((gx + 1.0f) * (float)W_ - 1.0f) * 0.5f;
            float fx0 = floorf(ix);
            float wx1 = ix - fx0;
            float wx0 = 1.0f - wx1;
            int x0 = (int)fx0;
            int x1 = x0 + 1;
            float a0 = ((x0 >= 0) & (x0 < W_)) ? wx0 : 0.0f;
            float a1 = ((x1 >= 0) & (x1 < W_)) ? wx1 : 0.0f;
            int cx0 = min(max(x0, 0), W_ - 1);
            int cx1 = min(max(x1, 0), W_ - 1);
            const float4* row = yT4 + (size_t)gr * (W_ * 4);
            float4 p0 = row[cx0 * 4 + ch4];
            float4 p1 = row[cx1 * 4 + ch4];
            v.x = a0 * p0.x + a1 * p1.x;
            v.y = a0 * p0.y + a1 * p1.y;
            v.z = a0 * p0.z + a1 * p1.z;
            v.w = a0 * p0.w + a1 * p1.w;
        }
        L[r * RSF4 + ch4 * WCH + wl] = v;
    }
    __syncthreads();

    int wl    = tid & (WCH - 1);
    int dbase = tid >> 5;                       // 0..15; handles d = dbase, dbase+16
    int w     = w0 + wl;

    // depth linear index: C0 + j*(16*HW) + hh*W
    int depC0 = (dbase * H_ + h0) * W_ + w;
    float dep_cur = depth[depC0];               // (hh=0, j=0) prefetched

#pragma unroll
    for (int hh = 0; hh < HCH; ++hh) {
        int h = h0 + hh;
        float2 sc  = thsc[hh];
        float theta = ((float)h + 0.5f) * (PI / (float)H_) - PI * 0.5f;

        long ob0 = (long)dbase * HW_ + (long)h * W_ + w;   // d = dbase
        long ob1 = ob0 + 16L * HW_;                        // d = dbase+16

        // ---- reference half: one x load serves both d's ----
        const float* xp = x + h * W_ + w;
#pragma unroll
        for (int ch = 0; ch < C_; ++ch) {
            float v = __ldg(xp + ch * HW_);
            out[(long)ch * NDHW_ + ob0] = v;
            out[(long)ch * NDHW_ + ob1] = v;
        }

#pragma unroll
        for (int j = 0; j < 2; ++j) {
            // software pipeline: prefetch next depth before consuming current
            int lin = hh * 2 + j + 1;
            int nj  = lin & 1;
            int nhh = lin >> 1;
            float dep_next = depth[depC0 + nj * (16 * HW_) +
                                   ((nhh < HCH) ? nhh : 0) * W_];

            float dep = dep_cur;
            float dth = atanf((dep * sc.x + BASELINE_) / (dep * sc.y)) - theta;
            float d_v = dth * ((float)H_ / PI);
            float y_px = (float)h + d_v;        // depth>0, cos(theta)>0 -> finite

            // exact reference y math (align_corners=False)
            float gy  = y_px / ((H_ - 1.0f) * 0.5f) - 1.0f;
            float iy  = ((gy + 1.0f) * (float)H_ - 1.0f) * 0.5f;
            float fy0 = floorf(iy);
            float wy1 = iy - fy0;
            float wy0 = 1.0f - wy1;
            int r0 = (int)fy0 - h0 + 1;          // provably in [0, ROWS_-2]

            const float4* L0 = L + r0 * RSF4 + wl;
            const float4* L1 = L0 + RSF4;

            long ob = (j == 0) ? ob0 : ob1;
            float* op = out + 16L * NDHW_ + ob;
#pragma unroll
            for (int ch4 = 0; ch4 < 4; ++ch4) {
                float4 u0 = L0[ch4 * WCH];
                float4 u1 = L1[ch4 * WCH];
                op[(long)(ch4 * 4 + 0) * NDHW_] = wy0 * u0.x + wy1 * u1.x;
                op[(long)(ch4 * 4 + 1) * NDHW_] = wy0 * u0.y + wy1 * u1.y;
                op[(long)(ch4 * 4 + 2) * NDHW_] = wy0 * u0.z + wy1 * u1.z;
                op[(long)(ch4 * 4 + 3) * NDHW_] = wy0 * u0.w + wy1 * u1.w;
            }

            dep_cur = dep_next;
        }
    }
}

extern "C" void kernel_launch(void* const* d_in, const int* in_sizes, int n_in,
                              void* d_out, int out_size) {
    const float* x     = (const float*)d_in[0];
    const float* y     = (const float*)d_in[1];
    const float* depth = (const float*)d_in[2];
    float* out = (float*)d_out;

    {
        int total = HW_;
        int threads = 256;
        transpose_y_kernel<<<(total + threads - 1) / threads, threads>>>(y);
    }
    {
        cudaFuncSetAttribute(cost_volume_kernel,
                             cudaFuncAttributeMaxDynamicSharedMemorySize,
                             SMEM_BYTES);
        dim3 grid(W_ / WCH, H_ / HCH);   // (16, 32) = 512 blocks
        cost_volume_kernel<<<grid, 512, SMEM_BYTES>>>(x, depth, out);
    }
}